// round 2
// baseline (speedup 1.0000x reference)
#include <cuda_runtime.h>
#include <cstdint>

// image: [64, 3, 512, 512] fp32  -> 50,331,648 elems
// block_switch: [64, 64] bool, serialized as int32 -> 4096 elems
// out = where(mask_full, -1.0f, image), mask expanded 8x8 per block.
//
// Pure streaming: 402 MB total traffic, HBM-bound. float4 path.

#define H_DIM 512
#define W_DIM 512
#define W4    (W_DIM / 4)        // 128 float4 per row

__global__ void __launch_bounds__(256) grid_crop_kernel(
    const float4* __restrict__ img,
    const int* __restrict__ sw,   // [64,64] bool-as-int32
    float4* __restrict__ out,
    int n4)
{
    int i = blockIdx.x * blockDim.x + threadIdx.x;
    if (i >= n4) return;

    // i indexes float4s over [B*C, H, W/4]
    int w4 = i & (W4 - 1);               // 0..127 (covers w = 4*w4 .. 4*w4+3)
    int h  = (i >> 7) & (H_DIM - 1);     // 0..511

    // mask index: (h/8)*64 + (w/8); w/8 == w4/2 since a w4-aligned float4
    // stays inside one 8-wide block.
    int m = __ldg(&sw[((h >> 3) << 6) | (w4 >> 1)]);

    float4 v = img[i];
    if (m) { v.x = -1.0f; v.y = -1.0f; v.z = -1.0f; v.w = -1.0f; }
    out[i] = v;
}

extern "C" void kernel_launch(void* const* d_in, const int* in_sizes, int n_in,
                              void* d_out, int out_size)
{
    // Robust input selection: image has 50,331,648 elems, mask has 4,096.
    const void* p_img = d_in[0];
    const void* p_sw  = d_in[1];
    if (n_in >= 2 && in_sizes[0] < in_sizes[1]) {
        p_img = d_in[1];
        p_sw  = d_in[0];
    }

    const float4* img = (const float4*)p_img;
    const int* sw = (const int*)p_sw;
    float4* out = (float4*)d_out;

    int n4 = out_size / 4;   // 12,582,912 float4s
    int threads = 256;
    int blocks = (n4 + threads - 1) / threads;
    grid_crop_kernel<<<blocks, threads>>>(img, sw, out, n4);
}

// round 3
// speedup vs baseline: 1.0065x; 1.0065x over previous
#include <cuda_runtime.h>
#include <cstdint>

// image: [64, 3, 512, 512] fp32 -> 50,331,648 elems; mask [64,64] bool-as-int32.
// out = where(mask8x8, -1.0f, image). Pure streaming, HBM-bound.
// Unroll x4 per thread: 4 independent LDG.128 in flight (MLP=4).

#define W4 128            // float4s per row (W=512)
#define UNROLL 4

__global__ void __launch_bounds__(256) grid_crop_kernel(
    const float4* __restrict__ img,
    const int* __restrict__ sw,      // [64,64] bool-as-int32
    float4* __restrict__ out)
{
    // Each block covers 1024 consecutive float4s. n4 = 12,582,912 = 12288 * 1024.
    int base = blockIdx.x * (256 * UNROLL) + threadIdx.x;

    int idx[UNROLL];
    float4 v[UNROLL];

    // Front-batch all loads: 4 independent LDG.128 per thread.
    #pragma unroll
    for (int k = 0; k < UNROLL; k++) {
        idx[k] = base + k * 256;
        v[k] = img[idx[k]];
    }

    #pragma unroll
    for (int k = 0; k < UNROLL; k++) {
        int w4 = idx[k] & (W4 - 1);          // 0..127
        int h  = (idx[k] >> 7) & 511;        // 0..511
        int m = __ldg(&sw[((h >> 3) << 6) | (w4 >> 1)]);
        if (m) { v[k].x = -1.0f; v[k].y = -1.0f; v[k].z = -1.0f; v[k].w = -1.0f; }
    }

    #pragma unroll
    for (int k = 0; k < UNROLL; k++) {
        out[idx[k]] = v[k];
    }
}

extern "C" void kernel_launch(void* const* d_in, const int* in_sizes, int n_in,
                              void* d_out, int out_size)
{
    const void* p_img = d_in[0];
    const void* p_sw  = d_in[1];
    if (n_in >= 2 && in_sizes[0] < in_sizes[1]) {
        p_img = d_in[1];
        p_sw  = d_in[0];
    }

    const float4* img = (const float4*)p_img;
    const int* sw = (const int*)p_sw;
    float4* out = (float4*)d_out;

    int n4 = out_size / 4;                      // 12,582,912
    int blocks = n4 / (256 * UNROLL);           // 12,288 exact
    grid_crop_kernel<<<blocks, 256>>>(img, sw, out);
}

// round 4
// speedup vs baseline: 1.0320x; 1.0253x over previous
#include <cuda_runtime.h>
#include <cstdint>

// image: [64, 3, 512, 512] fp32; mask [64,64] bool-as-int32 (rate ~0.5).
// out = where(mask8x8, -1.0f, image).
//
// Key optimization: masked outputs are constant -1.0 -> skip the image READ
// for those. One mask element = 8 floats = 32B = 1 DRAM sector = 2 float4
// threads, so predicated loads eliminate whole sectors of read traffic.
// Expected traffic: 201MB write + ~100MB read (vs 402MB unconditional).

#define W4 128            // float4s per row (W=512)
#define UNROLL 4

__global__ void __launch_bounds__(256) grid_crop_kernel(
    const float4* __restrict__ img,
    const int* __restrict__ sw,      // [64,64] bool-as-int32
    float4* __restrict__ out)
{
    int base = blockIdx.x * (256 * UNROLL) + threadIdx.x;

    int idx[UNROLL];
    int m[UNROLL];
    float4 v[UNROLL];

    // Mask lookups first (L1-resident, cheap).
    #pragma unroll
    for (int k = 0; k < UNROLL; k++) {
        idx[k] = base + k * 256;
        int w4 = idx[k] & (W4 - 1);          // 0..127
        int h  = (idx[k] >> 7) & 511;        // 0..511
        m[k] = __ldg(&sw[((h >> 3) << 6) | (w4 >> 1)]);
    }

    // Predicated loads: only unmasked sectors are fetched from DRAM.
    #pragma unroll
    for (int k = 0; k < UNROLL; k++) {
        v[k] = make_float4(-1.0f, -1.0f, -1.0f, -1.0f);
        if (!m[k]) v[k] = img[idx[k]];
    }

    #pragma unroll
    for (int k = 0; k < UNROLL; k++) {
        out[idx[k]] = v[k];
    }
}

extern "C" void kernel_launch(void* const* d_in, const int* in_sizes, int n_in,
                              void* d_out, int out_size)
{
    const void* p_img = d_in[0];
    const void* p_sw  = d_in[1];
    if (n_in >= 2 && in_sizes[0] < in_sizes[1]) {
        p_img = d_in[1];
        p_sw  = d_in[0];
    }

    const float4* img = (const float4*)p_img;
    const int* sw = (const int*)p_sw;
    float4* out = (float4*)d_out;

    int n4 = out_size / 4;                      // 12,582,912
    int blocks = n4 / (256 * UNROLL);           // 12,288 exact
    grid_crop_kernel<<<blocks, 256>>>(img, sw, out);
}